// round 9
// baseline (speedup 1.0000x reference)
#include <cuda_runtime.h>
#include <math.h>
#include <cstdint>

// SupConLoss fused kernel for B=8192, D=128, T=0.1.
// Structure is IDENTICAL to the round-1 PASSING kernel (3 launches, 1D grid,
// scalar device accumulators, online-softmax epilogue). Single change: the
// 4x4 scalar-fmaf micro-kernel becomes packed f32x2 FMA (SASS FFMA2, 2x fp32
// MAC per FMA-pipe slot). The A tile is staged with duplicated values (a,a)
// so both operands come straight from 16B shared loads -- no packing ops.

#define BSZ   8192
#define DD    128
#define BM    64
#define BN    64
#define PADA  132         // duplicated-A row stride in floats (528B, 16B-mult)
#define PADB  72          // B row stride in floats (288B, 16B-mult)
#define NTHR  256
#define INV_T 10.0f

// global accumulators (device globals: no allocation allowed)
__device__ float g_sum;
__device__ float g_cnt;

__global__ void supcon_zero_kernel() {
    g_sum = 0.0f;
    g_cnt = 0.0f;
}

__global__ void supcon_finalize_kernel(float* __restrict__ out) {
    float c = g_cnt;
    out[0] = (c > 0.0f) ? (g_sum / c) : 0.0f;
}

__device__ __forceinline__ void unpack2(unsigned long long v, float& x, float& y) {
    asm("mov.b64 {%0, %1}, %2;" : "=f"(x), "=f"(y) : "l"(v));
}
#define FMA2(acc, a, b) \
    asm("fma.rn.f32x2 %0, %1, %2, %0;" : "+l"(acc) : "l"(a), "l"(b))

extern __shared__ float smem[];

__global__ __launch_bounds__(NTHR)
void supcon_main_kernel(const float* __restrict__ F,
                        const long long* __restrict__ L) {
    float* As2 = smem;                        // [DD][PADA] duplicated pairs
    float* Bs  = smem + DD * PADA;            // [DD][PADB]
    int*   labA = (int*)(smem + DD * PADA + DD * PADB);   // [BM]
    int*   labB = labA + BM;                              // [BN]

    const int tid = threadIdx.x;
    const int tx  = tid & 15;                 // 0..15 -> column group
    const int ty  = tid >> 4;                 // 0..15 -> row group
    const int row0 = blockIdx.x * BM;

    // ---- load A tile, transposed + duplicated (a,a) pairs ----
    {
        const int c = tid >> 2;               // 0..63 local row
        const int q = tid & 3;
        const float4* src = (const float4*)(F + (size_t)(row0 + c) * DD);
        #pragma unroll
        for (int i = 0; i < 8; i++) {
            int kf = q + i * 4;               // 0..31 float4 index along D
            float4 v = src[kf];
            int k = kf * 4;
            As2[(k + 0) * PADA + 2 * c] = v.x; As2[(k + 0) * PADA + 2 * c + 1] = v.x;
            As2[(k + 1) * PADA + 2 * c] = v.y; As2[(k + 1) * PADA + 2 * c + 1] = v.y;
            As2[(k + 2) * PADA + 2 * c] = v.z; As2[(k + 2) * PADA + 2 * c + 1] = v.z;
            As2[(k + 3) * PADA + 2 * c] = v.w; As2[(k + 3) * PADA + 2 * c + 1] = v.w;
        }
        if (tid < BM) labA[tid] = (int)L[row0 + tid];
    }

    // per-thread running row state for rows ty*4+i (replicated across the 16
    // lanes sharing ty; they all compute identical reduced values)
    float m[4], s[4], ps[4], pc[4];
    #pragma unroll
    for (int i = 0; i < 4; i++) {
        m[i] = -INFINITY; s[i] = 0.0f; ps[i] = 0.0f; pc[i] = 0.0f;
    }

    const int la0 = ty * 4;

    for (int jt = 0; jt < BSZ / BN; jt++) {
        const int col0 = jt * BN;
        __syncthreads();                      // guard Bs reuse (and As on jt=0)

        // ---- load B tile, transposed ----
        {
            const int c = tid >> 2;
            const int q = tid & 3;
            const float4* src = (const float4*)(F + (size_t)(col0 + c) * DD);
            #pragma unroll
            for (int i = 0; i < 8; i++) {
                int kf = q + i * 4;
                float4 v = src[kf];
                int k = kf * 4;
                Bs[(k + 0) * PADB + c] = v.x;
                Bs[(k + 1) * PADB + c] = v.y;
                Bs[(k + 2) * PADB + c] = v.z;
                Bs[(k + 3) * PADB + c] = v.w;
            }
            if (tid < BN) labB[tid] = (int)L[col0 + tid];
        }
        __syncthreads();

        // ---- 4x4 register-tiled GEMM via packed f32x2 FMA ----
        unsigned long long acc[4][2];
        #pragma unroll
        for (int i = 0; i < 4; i++) { acc[i][0] = 0ull; acc[i][1] = 0ull; }

        #pragma unroll 4
        for (int k = 0; k < DD; k++) {
            // A: 4 duplicated pairs (a0,a0)(a1,a1)(a2,a2)(a3,a3) = 2x 16B
            ulonglong2 A01 = *(const ulonglong2*)&As2[k * PADA + ty * 8];
            ulonglong2 A23 = *(const ulonglong2*)&As2[k * PADA + ty * 8 + 4];
            // B: 4 cols as 2 packed pairs (b0,b1)(b2,b3) = 1x 16B
            ulonglong2 Bv  = *(const ulonglong2*)&Bs[k * PADB + tx * 4];
            FMA2(acc[0][0], A01.x, Bv.x); FMA2(acc[0][1], A01.x, Bv.y);
            FMA2(acc[1][0], A01.y, Bv.x); FMA2(acc[1][1], A01.y, Bv.y);
            FMA2(acc[2][0], A23.x, Bv.x); FMA2(acc[2][1], A23.x, Bv.y);
            FMA2(acc[3][0], A23.y, Bv.x); FMA2(acc[3][1], A23.y, Bv.y);
        }

        // column labels for this thread's 4 columns
        int lb[4];
        #pragma unroll
        for (int j = 0; j < 4; j++) lb[j] = labB[tx * 4 + j];

        // ---- per-row reduction over this 64-col tile + online merge ----
        #pragma unroll
        for (int i = 0; i < 4; i++) {
            const int gi = row0 + la0 + i;
            const int la = labA[la0 + i];

            float sc[4];
            unpack2(acc[i][0], sc[0], sc[1]);
            unpack2(acc[i][1], sc[2], sc[3]);

            // tile max (diag INCLUDED, matching reference)
            float vm = -INFINITY;
            #pragma unroll
            for (int j = 0; j < 4; j++) vm = fmaxf(vm, sc[j] * INV_T);
            #pragma unroll
            for (int off = 8; off >= 1; off >>= 1)
                vm = fmaxf(vm, __shfl_xor_sync(0xffffffffu, vm, off));

            // exp-sum (diag excluded), positive sum & count
            float ls = 0.0f, lp = 0.0f, lc = 0.0f;
            #pragma unroll
            for (int j = 0; j < 4; j++) {
                const int gj = col0 + tx * 4 + j;
                const float v = sc[j] * INV_T;
                if (gj != gi) {
                    ls += __expf(v - vm);
                    if (lb[j] == la) { lp += v; lc += 1.0f; }
                }
            }
            #pragma unroll
            for (int off = 8; off >= 1; off >>= 1) {
                ls += __shfl_xor_sync(0xffffffffu, ls, off);
                lp += __shfl_xor_sync(0xffffffffu, lp, off);
                lc += __shfl_xor_sync(0xffffffffu, lc, off);
            }

            // online-softmax merge into running state
            const float mn = fmaxf(m[i], vm);
            s[i]  = s[i] * __expf(m[i] - mn) + ls * __expf(vm - mn);
            m[i]  = mn;
            ps[i] += lp;
            pc[i] += lc;
        }
    }

    // ---- per-row contribution -> global accumulators ----
    if (tx == 0) {
        #pragma unroll
        for (int i = 0; i < 4; i++) {
            if (pc[i] > 0.0f) {
                float mean_lp = ps[i] / pc[i] - m[i] - logf(s[i] + 1e-12f);
                atomicAdd(&g_sum, -mean_lp);
                atomicAdd(&g_cnt, 1.0f);
            }
        }
    }
}

extern "C" void kernel_launch(void* const* d_in, const int* in_sizes, int n_in,
                              void* d_out, int out_size) {
    const float*     F = (const float*)d_in[0];
    const long long* L = (const long long*)d_in[1];
    float*           out = (float*)d_out;

    const int smem_bytes =
        (DD * PADA + DD * PADB) * sizeof(float) + (BM + BN) * sizeof(int);
    cudaFuncSetAttribute(supcon_main_kernel,
                         cudaFuncAttributeMaxDynamicSharedMemorySize, smem_bytes);

    supcon_zero_kernel<<<1, 1>>>();
    supcon_main_kernel<<<BSZ / BM, NTHR, smem_bytes>>>(F, L);
    supcon_finalize_kernel<<<1, 1>>>(out);
}

// round 10
// speedup vs baseline: 1.4626x; 1.4626x over previous
#include <cuda_runtime.h>
#include <math.h>
#include <cstdint>

// ============================================================================
// SupConLoss, B=8192, D=128, T=0.1. Round 10.
//
// Proven-safe skeleton (3 launches, 1D grid, scalar device accumulators,
// global-only atomics) + bigger tiles. HARD CONSTRAINT discovered R3-R9:
// dynamic smem >= ~192KB faults (CUDA 717) on this target; keep <= ~105KB.
//
// BM=64 rows/CTA (grid 128), BN=128 cols/tile (64 tiles swept per CTA).
// 256 threads; micro-tile 4 rows x 8 cols per thread via 16 packed f32x2
// accumulators holding ROW PAIRS: A operands are natural (a_2r, a_2r+1)
// pairs (plain 16B loads, no packing), B is duplicated (b,b) via mov.b64.
// Inner loop: 3 LDS.128 + 8 MOV + 16 FMA2 = 27 instr / 32 MACs.
//
// Epilogue: log-softmax is shift-invariant and diag sim == 1 dominates each
// row max, so a constant shift of 10 replaces the online max exactly.
// s/ps/pc accumulate in registers across all tiles; one butterfly + global
// atomics at the end.
// ============================================================================

#define BSZ   8192
#define DD    128
#define BM    64
#define BN    128
#define NTHR  256
#define JT    (BSZ / BN)          // 64 tiles
#define PADA  68                  // A row stride in floats (272B = 17*16B)
#define PADB  132                 // B row stride in floats (528B = 33*16B)

// smem: A[128][68] | B[128][132] | labA[64] | labB[128]  = 103168 B
#define SM_A_FLOATS (DD * PADA)
#define SM_B_FLOATS (DD * PADB)
#define SMEM_TOTAL  ((SM_A_FLOATS + SM_B_FLOATS) * 4 + (BM + BN) * 4)

// global accumulators
__device__ float g_sum;
__device__ float g_cnt;

__global__ void supcon_zero_kernel() { g_sum = 0.0f; g_cnt = 0.0f; }

__global__ void supcon_finalize_kernel(float* __restrict__ out) {
    float c = g_cnt;
    out[0] = (c > 0.0f) ? (g_sum / c) : 0.0f;
}

__device__ __forceinline__ void unpack2(unsigned long long v, float& x, float& y) {
    asm("mov.b64 {%0, %1}, %2;" : "=f"(x), "=f"(y) : "l"(v));
}
__device__ __forceinline__ unsigned long long dup2(float x) {
    unsigned long long r;
    asm("mov.b64 %0, {%1, %1};" : "=l"(r) : "f"(x));
    return r;
}
#define FMA2(acc, a, b) \
    asm("fma.rn.f32x2 %0, %1, %2, %0;" : "+l"(acc) : "l"(a), "l"(b))

// B chunk swizzle: 16B chunk cc (0..31) of a k-row stored at cc ^ (cc>>3).
// Spreads the tx-strided reads (2tx, 2tx+1) to <=2-way bank groups.
__device__ __forceinline__ int bswz(int cc) { return cc ^ (cc >> 3); }

extern __shared__ float smem[];

__global__ __launch_bounds__(NTHR)
void supcon_main_kernel(const float* __restrict__ F,
                        const long long* __restrict__ L) {
    float* As = smem;                            // [DD][PADA] k-major
    float* Bs = smem + SM_A_FLOATS;              // [DD][PADB] k-major swizzled
    int*   labA = (int*)(smem + SM_A_FLOATS + SM_B_FLOATS);   // [BM]
    int*   labB = labA + BM;                                  // [BN]

    const int tid = threadIdx.x;
    const int tx  = tid & 15;                    // 0..15 -> 8 cols each
    const int ty  = tid >> 4;                    // 0..15 -> 4 rows each
    const int row0 = blockIdx.x * BM;

    // ---- stage A tile (64 rows), transposed k-major, once ----
    {
        const int c = tid >> 2;                  // 0..63 local row
        const int q = tid & 3;
        const float4* src = (const float4*)(F + (size_t)(row0 + c) * DD);
        #pragma unroll
        for (int i = 0; i < 8; i++) {
            int kf = q + i * 4;                  // float4 index along D
            float4 v = src[kf];
            int k = kf * 4;
            As[(k + 0) * PADA + c] = v.x;
            As[(k + 1) * PADA + c] = v.y;
            As[(k + 2) * PADA + c] = v.z;
            As[(k + 3) * PADA + c] = v.w;
        }
        if (tid < BM) labA[tid] = (int)L[row0 + tid];
    }

    // per-thread running state for rows ty*4+i (replicated across tx lanes)
    float s[4], ps[4], pc[4];
    #pragma unroll
    for (int i = 0; i < 4; i++) { s[i] = 0.0f; ps[i] = 0.0f; pc[i] = 0.0f; }

    int la[4];
    // labA written above; read after first barrier below

    const int myrow = ty * 4;

    for (int jt = 0; jt < JT; jt++) {
        const int col0 = jt * BN;
        __syncthreads();                         // Bs reuse guard (As on jt=0)

        // ---- stage B tile (128 rows), transposed k-major + chunk swizzle ---
        {
            const int cb = tid >> 1;             // 0..127 local col (row of F)
            const int q  = tid & 1;
            const float4* src = (const float4*)(F + (size_t)(col0 + cb) * DD);
            // fixed column position within a k-row after swizzle
            const int ppos = bswz(cb >> 2) * 4 + (cb & 3);
            float4 Rv[16];
            #pragma unroll
            for (int i = 0; i < 16; i++) Rv[i] = src[q + 2 * i];
            #pragma unroll
            for (int i = 0; i < 16; i++) {
                int k = (q + 2 * i) * 4;
                Bs[(k + 0) * PADB + ppos] = Rv[i].x;
                Bs[(k + 1) * PADB + ppos] = Rv[i].y;
                Bs[(k + 2) * PADB + ppos] = Rv[i].z;
                Bs[(k + 3) * PADB + ppos] = Rv[i].w;
            }
            if (tid < BN) labB[tid] = (int)L[col0 + tid];
        }
        __syncthreads();

        if (jt == 0) {
            #pragma unroll
            for (int i = 0; i < 4; i++) la[i] = labA[myrow + i];
        }

        // ---- 4x8 register tile: 16 packed row-pair accumulators ----
        unsigned long long acc[2][8];
        #pragma unroll
        for (int rp = 0; rp < 2; rp++)
            #pragma unroll
            for (int j = 0; j < 8; j++) acc[rp][j] = 0ull;

        const int sc0 = bswz(2 * tx) * 4;        // swizzled float offsets of
        const int sc1 = bswz(2 * tx + 1) * 4;    // this thread's two B chunks

        #pragma unroll 4
        for (int k = 0; k < DD; k++) {
            // A: rows ty*4..+3 as two natural 64-bit pairs (one 16B load)
            ulonglong2 Ap = *(const ulonglong2*)&As[k * PADA + myrow];
            // B: 8 cols as two 16B loads, then duplicate each col
            float4 b03 = *(const float4*)&Bs[k * PADB + sc0];
            float4 b47 = *(const float4*)&Bs[k * PADB + sc1];
            unsigned long long bd[8];
            bd[0] = dup2(b03.x); bd[1] = dup2(b03.y);
            bd[2] = dup2(b03.z); bd[3] = dup2(b03.w);
            bd[4] = dup2(b47.x); bd[5] = dup2(b47.y);
            bd[6] = dup2(b47.z); bd[7] = dup2(b47.w);
            #pragma unroll
            for (int j = 0; j < 8; j++) {
                FMA2(acc[0][j], Ap.x, bd[j]);    // rows 0,1
                FMA2(acc[1][j], Ap.y, bd[j]);    // rows 2,3
            }
        }

        // ---- epilogue: constant-shift softmax terms + positive sums ----
        #pragma unroll
        for (int j = 0; j < 8; j++) {
            const int gj  = col0 + tx * 8 + j;
            const int lbj = labB[tx * 8 + j];
            #pragma unroll
            for (int rp = 0; rp < 2; rp++) {
                float v0, v1;
                unpack2(acc[rp][j], v0, v1);
                const int i0 = 2 * rp, i1 = 2 * rp + 1;
                const int gi0 = row0 + myrow + i0;
                const int gi1 = row0 + myrow + i1;
                float sv0 = v0 * 10.0f, sv1 = v1 * 10.0f;
                if (gj != gi0) {
                    s[i0] += __expf(sv0 - 10.0f);
                    if (lbj == la[i0]) { ps[i0] += sv0; pc[i0] += 1.0f; }
                }
                if (gj != gi1) {
                    s[i1] += __expf(sv1 - 10.0f);
                    if (lbj == la[i1]) { ps[i1] += sv1; pc[i1] += 1.0f; }
                }
            }
        }
    }

    // ---- reduce over the 16 tx lanes (within half-warp), then contribute ---
    #pragma unroll
    for (int i = 0; i < 4; i++) {
        #pragma unroll
        for (int off = 8; off >= 1; off >>= 1) {
            s[i]  += __shfl_xor_sync(0xffffffffu, s[i],  off);
            ps[i] += __shfl_xor_sync(0xffffffffu, ps[i], off);
            pc[i] += __shfl_xor_sync(0xffffffffu, pc[i], off);
        }
    }
    if (tx == 0) {
        #pragma unroll
        for (int i = 0; i < 4; i++) {
            if (pc[i] > 0.0f) {
                // shift-invariant: max == 10 (diag) up to fp eps; exact cancel
                float mlp = ps[i] / pc[i] - 10.0f - logf(s[i] + 1e-12f);
                atomicAdd(&g_sum, -mlp);
                atomicAdd(&g_cnt, 1.0f);
            }
        }
    }
}

extern "C" void kernel_launch(void* const* d_in, const int* in_sizes, int n_in,
                              void* d_out, int out_size) {
    const float*     F = (const float*)d_in[0];
    const long long* L = (const long long*)d_in[1];
    float*           out = (float*)d_out;

    cudaFuncSetAttribute(supcon_main_kernel,
                         cudaFuncAttributeMaxDynamicSharedMemorySize, SMEM_TOTAL);

    supcon_zero_kernel<<<1, 1>>>();
    supcon_main_kernel<<<BSZ / BM, NTHR, SMEM_TOTAL>>>(F, L);
    supcon_finalize_kernel<<<1, 1>>>(out);
}

// round 12
// speedup vs baseline: 2.5613x; 1.7513x over previous
#include <cuda_runtime.h>
#include <math.h>
#include <cstdint>

// ============================================================================
// SupConLoss, B=8192, D=128, T=0.1. Round 12: symmetric S on the R10 skeleton.
//
// S = F F^T is symmetric: each off-diagonal tile credits BOTH its rows'
// softmax/positive sums and (transposed) its columns'. Only block-upper-
// triangle tiles are computed: row-blocks BM=64 (i=0..127), col-tiles BN=128
// (j=0..63), tile (i,j) iff j >= i>>1. Diagonal 128-blocks (j == i>>1) are
// fully covered by row-blocks 2j,2j+1 -> row credit only, diag element
// masked. Row-block pair (m,127-m) has 65 tiles; split 33/32 over CTAs
// 2m,2m+1 -> 128 balanced CTAs (~33 tiles each vs 64 in R10).
//
// TOOLCHAIN RULES (hard-won R3-R11): no cp.async/ldmatrix/mma.sync/tcgen05;
// __device__ arrays ONLY with scalar access + no align attrs (vector loads /
// aligned attrs on device symbols correlate 7/7 with CUDA 717); smem ~103KB
// max; fma.rn.f32x2 is real FFMA2 and safe.
//
// Constant shift 10 replaces the online max (log-softmax shift-invariance;
// diag sim == 1 dominates). loss = mean_{pc>0} -(ps/pc - 10 - log(s+1e-12)),
// ps accumulated pre-scaled by 10.
// ============================================================================

#define BSZ   8192
#define DD    128
#define BM    64
#define BN    128
#define NTHR  256
#define PADA  68
#define PADB  132
#define C_EXP 14.4269504088896341f

#define SM_A_FLOATS (DD * PADA)
#define SM_B_FLOATS (DD * PADB)
#define SMEM_TOTAL  ((SM_A_FLOATS + SM_B_FLOATS) * 4 + (BM + BN) * 4)  // 103168

// ---- device scratch: plain arrays, scalar access only ----------------------
__device__ float g_s[BSZ];     // sum_{j!=i} exp(10*sim-10)
__device__ float g_ps[BSZ];    // sum_pos 10*sim (diag excluded)
__device__ float g_pc[BSZ];    // positive count
__device__ float g_sum;
__device__ float g_cnt;

// ---- helpers ---------------------------------------------------------------
__device__ __forceinline__ float ex2f(float x) {
    float y;
    asm("ex2.approx.ftz.f32 %0, %1;" : "=f"(y) : "f"(x));
    return y;
}
__device__ __forceinline__ void unpack2(unsigned long long v, float& x, float& y) {
    asm("mov.b64 {%0, %1}, %2;" : "=f"(x), "=f"(y) : "l"(v));
}
__device__ __forceinline__ unsigned long long dup2(float x) {
    unsigned long long r;
    asm("mov.b64 %0, {%1, %1};" : "=l"(r) : "f"(x));
    return r;
}
#define FMA2(acc, a, b) \
    asm("fma.rn.f32x2 %0, %1, %2, %0;" : "+l"(acc) : "l"(a), "l"(b))
__device__ __forceinline__ int bswz(int cc) { return cc ^ (cc >> 3); }

// ---- aux kernels (scalar device-array access only) -------------------------
__global__ void supcon_zero() {
    int i = blockIdx.x * blockDim.x + threadIdx.x;   // 32*256 = BSZ threads
    g_s[i] = 0.0f; g_ps[i] = 0.0f; g_pc[i] = 0.0f;
    if (i == 0) { g_sum = 0.0f; g_cnt = 0.0f; }
}

__global__ void supcon_reduce() {
    int r = blockIdx.x * blockDim.x + threadIdx.x;   // BSZ threads
    float pcv = g_pc[r];
    float ls = 0.0f, lc = 0.0f;
    if (pcv > 0.0f) {
        float mlp = g_ps[r] / pcv - 10.0f - logf(g_s[r] + 1e-12f);
        ls = -mlp; lc = 1.0f;
    }
    #pragma unroll
    for (int o = 16; o >= 1; o >>= 1) {
        ls += __shfl_xor_sync(0xffffffffu, ls, o);
        lc += __shfl_xor_sync(0xffffffffu, lc, o);
    }
    if ((threadIdx.x & 31) == 0) {
        atomicAdd(&g_sum, ls);
        atomicAdd(&g_cnt, lc);
    }
}

__global__ void supcon_write(float* __restrict__ out) {
    float c = g_cnt;
    out[0] = (c > 0.0f) ? (g_sum / c) : 0.0f;
}

// ---- main kernel ------------------------------------------------------------
extern __shared__ float smem[];

__global__ __launch_bounds__(NTHR)
void supcon_main_kernel(const float* __restrict__ F,
                        const long long* __restrict__ L) {
    float* As = smem;                          // [DD][PADA] k-major
    float* Bs = smem + SM_A_FLOATS;            // [DD][PADB] k-major swizzled
    float* colbuf = Bs;                        // [3][16][BN] = 24KB, aliases Bs
    int*   labA = (int*)(smem + SM_A_FLOATS + SM_B_FLOATS);   // [BM]
    int*   labB = labA + BM;                                  // [BN]

    const int tid = threadIdx.x;
    const int tx  = tid & 15;
    const int ty  = tid >> 4;
    const int myrow = ty * 4;

    // balanced triangle schedule: CTA pair (2m, 2m+1) covers row-blocks m and
    // 127-m (65 tiles total), split 33/32.
    const int m = blockIdx.x >> 1, half = blockIdx.x & 1;
    const int ba = m, bb = 127 - m;
    const int Ta = 64 - (ba >> 1);
    const int tstart = half ? 33 : 0;
    const int tend   = half ? 65 : 33;

    float s[4]  = {0.f, 0.f, 0.f, 0.f};
    float ps[4] = {0.f, 0.f, 0.f, 0.f};
    float pc[4] = {0.f, 0.f, 0.f, 0.f};
    int la[4];
    int cur_i = -1;

    const int sc0 = bswz(2 * tx) * 4;
    const int sc1 = bswz(2 * tx + 1) * 4;

    for (int t = tstart; t < tend; t++) {
        int i, j;
        if (t < Ta) { i = ba; j = (ba >> 1) + t; }
        else        { i = bb; j = (bb >> 1) + (t - Ta); }
        const int row0 = i * BM;
        const int col0 = j * BN;
        const bool diag = (j == (i >> 1));
        const bool newA = (i != cur_i);

        // ---- row-block switch: flush row state, restage A ----
        if (newA) {
            if (cur_i >= 0) {
                #pragma unroll
                for (int r = 0; r < 4; r++) {
                    float v = s[r], vp = ps[r], vc = pc[r];
                    #pragma unroll
                    for (int off = 8; off >= 1; off >>= 1) {
                        v  += __shfl_xor_sync(0xffffffffu, v,  off);
                        vp += __shfl_xor_sync(0xffffffffu, vp, off);
                        vc += __shfl_xor_sync(0xffffffffu, vc, off);
                    }
                    if (tx == 0) {
                        int gr = cur_i * BM + myrow + r;
                        atomicAdd(&g_s[gr],  v);
                        atomicAdd(&g_ps[gr], vp);
                        atomicAdd(&g_pc[gr], vc);
                    }
                    s[r] = 0.f; ps[r] = 0.f; pc[r] = 0.f;
                }
            }
            __syncthreads();                   // all As/colbuf readers done
            {
                const int c = tid >> 2, q = tid & 3;
                const float4* src = (const float4*)(F + (size_t)(row0 + c) * DD);
                #pragma unroll
                for (int i2 = 0; i2 < 8; i2++) {
                    int kf = q + i2 * 4;
                    float4 v = src[kf];
                    int k = kf * 4;
                    As[(k + 0) * PADA + c] = v.x;
                    As[(k + 1) * PADA + c] = v.y;
                    As[(k + 2) * PADA + c] = v.z;
                    As[(k + 3) * PADA + c] = v.w;
                }
                if (tid < BM) labA[tid] = (int)L[row0 + tid];
            }
            cur_i = i;
        }

        __syncthreads();                       // As ready / Bs+colbuf free
        // ---- stage B tile (R10-proven pattern) ----
        {
            const int cb = tid >> 1, q = tid & 1;
            const float4* src = (const float4*)(F + (size_t)(col0 + cb) * DD);
            const int ppos = bswz(cb >> 2) * 4 + (cb & 3);
            float4 Rv[16];
            #pragma unroll
            for (int i2 = 0; i2 < 16; i2++) Rv[i2] = src[q + 2 * i2];
            #pragma unroll
            for (int i2 = 0; i2 < 16; i2++) {
                int k = (q + 2 * i2) * 4;
                Bs[(k + 0) * PADB + ppos] = Rv[i2].x;
                Bs[(k + 1) * PADB + ppos] = Rv[i2].y;
                Bs[(k + 2) * PADB + ppos] = Rv[i2].z;
                Bs[(k + 3) * PADB + ppos] = Rv[i2].w;
            }
            if (tid < BN) labB[tid] = (int)L[col0 + tid];
        }
        __syncthreads();

        if (newA) {
            #pragma unroll
            for (int i2 = 0; i2 < 4; i2++) la[i2] = labA[myrow + i2];
        }

        // ---- 4x8 register tile, packed row-pair accumulators (R10) ----
        unsigned long long acc[2][8];
        #pragma unroll
        for (int rp = 0; rp < 2; rp++)
            #pragma unroll
            for (int jj = 0; jj < 8; jj++) acc[rp][jj] = 0ull;

        #pragma unroll 4
        for (int k = 0; k < DD; k++) {
            ulonglong2 Ap = *(const ulonglong2*)&As[k * PADA + myrow];
            float4 b03 = *(const float4*)&Bs[k * PADB + sc0];
            float4 b47 = *(const float4*)&Bs[k * PADB + sc1];
            unsigned long long bd[8];
            bd[0] = dup2(b03.x); bd[1] = dup2(b03.y);
            bd[2] = dup2(b03.z); bd[3] = dup2(b03.w);
            bd[4] = dup2(b47.x); bd[5] = dup2(b47.y);
            bd[6] = dup2(b47.z); bd[7] = dup2(b47.w);
            #pragma unroll
            for (int jj = 0; jj < 8; jj++) {
                FMA2(acc[0][jj], Ap.x, bd[jj]);
                FMA2(acc[1][jj], Ap.y, bd[jj]);
            }
        }

        // ---- epilogue: row credit always; column credit if off-diagonal ----
        float cs[8], cps[8], cpc[8];
        #pragma unroll
        for (int jj = 0; jj < 8; jj++) { cs[jj] = 0.f; cps[jj] = 0.f; cpc[jj] = 0.f; }

        #pragma unroll
        for (int jj = 0; jj < 8; jj++) {
            const int gj  = col0 + tx * 8 + jj;
            const int lbj = labB[tx * 8 + jj];
            #pragma unroll
            for (int rp = 0; rp < 2; rp++) {
                float v0, v1;
                unpack2(acc[rp][jj], v0, v1);
                #pragma unroll
                for (int e2 = 0; e2 < 2; e2++) {
                    const float v = e2 ? v1 : v0;
                    const int ii = 2 * rp + e2;
                    const int gi = row0 + myrow + ii;
                    if (!diag || gj != gi) {
                        float e = ex2f(fmaf(v, C_EXP, -C_EXP));
                        s[ii] += e; cs[jj] += e;
                        if (lbj == la[ii]) {
                            float sv = v * 10.0f;
                            ps[ii] += sv; pc[ii] += 1.0f;
                            cps[jj] += sv; cpc[jj] += 1.0f;
                        }
                    }
                }
            }
        }

        if (!diag) {
            __syncthreads();                   // all threads done reading Bs
            #pragma unroll
            for (int jj = 0; jj < 8; jj++) {
                int cix = ty * BN + tx * 8 + jj;
                colbuf[cix]        = cs[jj];
                colbuf[2048 + cix] = cps[jj];
                colbuf[4096 + cix] = cpc[jj];
            }
            __syncthreads();
            if (tid < BN) {
                float a = 0.f, b = 0.f, c = 0.f;
                #pragma unroll
                for (int g2 = 0; g2 < 16; g2++) {
                    a += colbuf[g2 * BN + tid];
                    b += colbuf[2048 + g2 * BN + tid];
                    c += colbuf[4096 + g2 * BN + tid];
                }
                atomicAdd(&g_s[col0 + tid],  a);
                atomicAdd(&g_ps[col0 + tid], b);
                atomicAdd(&g_pc[col0 + tid], c);
            }
        }
    }

    // final flush of the last row-block's state
    #pragma unroll
    for (int r = 0; r < 4; r++) {
        float v = s[r], vp = ps[r], vc = pc[r];
        #pragma unroll
        for (int off = 8; off >= 1; off >>= 1) {
            v  += __shfl_xor_sync(0xffffffffu, v,  off);
            vp += __shfl_xor_sync(0xffffffffu, vp, off);
            vc += __shfl_xor_sync(0xffffffffu, vc, off);
        }
        if (tx == 0) {
            int gr = cur_i * BM + myrow + r;
            atomicAdd(&g_s[gr],  v);
            atomicAdd(&g_ps[gr], vp);
            atomicAdd(&g_pc[gr], vc);
        }
    }
}

// ---- launch ----------------------------------------------------------------
extern "C" void kernel_launch(void* const* d_in, const int* in_sizes, int n_in,
                              void* d_out, int out_size) {
    const float*     F = (const float*)d_in[0];
    const long long* L = (const long long*)d_in[1];
    float*           out = (float*)d_out;

    cudaFuncSetAttribute(supcon_main_kernel,
                         cudaFuncAttributeMaxDynamicSharedMemorySize, SMEM_TOTAL);

    supcon_zero<<<BSZ / 256, 256>>>();
    supcon_main_kernel<<<128, NTHR, SMEM_TOTAL>>>(F, L);
    supcon_reduce<<<BSZ / 256, 256>>>();
    supcon_write<<<1, 1>>>(out);
}

// round 13
// speedup vs baseline: 2.7716x; 1.0821x over previous
#include <cuda_runtime.h>
#include <math.h>
#include <cstdint>

// ============================================================================
// SupConLoss, B=8192, D=128, T=0.1. Round 13: 8x8 micro-tile, 128x128 tiles.
//
// R12 was shared-memory-BW bound (48B per 32 MACs = 96 cyc/k vs 64 FMA2).
// This round: 8x8 per-thread tile -> 64B per 64 MACs (1.0 B/MAC), LDS and
// FMA2 both ~128 cyc per 16K MACs. BM=BN=128; full A (67.6KB) + HALF-K B
// (33.8KB) staged twice per tile keeps smem at 102400B (<= proven 103168).
//
// Symmetric triangle schedule on the 64x64 grid of 128-tiles (j >= i, 2080
// tiles): diag tiles row-credit only (element diag masked), off-diag tiles
// credit rows AND columns (transpose). Pair (m,63-m) = 65 tiles split
// 17/16/16/16 across 4 CTAs -> 128 balanced CTAs.
//
// TOOLCHAIN RULES (R3-R12): no cp.async/ldmatrix/mma.sync/tcgen05; __device__
// arrays scalar-access only, no align attrs (vector access to device symbols
// => CUDA 717); fma.rn.f32x2 is real FFMA2 and safe; smem <= ~103KB proven.
//
// Math: constant shift 10 (log-softmax shift-invariance; diag sim == 1
// dominates). loss = mean_{pc>0} -(ps/pc - 10 - log(s+1e-12)), ps pre-scaled.
// ============================================================================

#define BSZ   8192
#define DD    128
#define BM    128
#define BN    128
#define NTHR  256
#define PADA  132
#define PADB  132
#define C_EXP 14.4269504088896341f

#define SM_A_FLOATS (DD * PADA)          // 16896
#define SM_B_FLOATS (64 * PADB)          // 8448 (half-k B)
#define SMEM_TOTAL  ((SM_A_FLOATS + SM_B_FLOATS) * 4 + (BM + BN) * 4)  // 102400

// ---- device scratch: plain arrays, scalar access only ----------------------
__device__ float g_s[BSZ];
__device__ float g_ps[BSZ];
__device__ float g_pc[BSZ];
__device__ float g_sum;
__device__ float g_cnt;

// ---- helpers ---------------------------------------------------------------
__device__ __forceinline__ float ex2f(float x) {
    float y;
    asm("ex2.approx.ftz.f32 %0, %1;" : "=f"(y) : "f"(x));
    return y;
}
__device__ __forceinline__ void unpack2(unsigned long long v, float& x, float& y) {
    asm("mov.b64 {%0, %1}, %2;" : "=f"(x), "=f"(y) : "l"(v));
}
__device__ __forceinline__ unsigned long long dup2(float x) {
    unsigned long long r;
    asm("mov.b64 %0, {%1, %1};" : "=l"(r) : "f"(x));
    return r;
}
#define FMA2(acc, a, b) \
    asm("fma.rn.f32x2 %0, %1, %2, %0;" : "+l"(acc) : "l"(a), "l"(b))
__device__ __forceinline__ int bswz(int cc) { return cc ^ (cc >> 3); }

// ---- aux kernels (verbatim from passing R12) -------------------------------
__global__ void supcon_zero() {
    int i = blockIdx.x * blockDim.x + threadIdx.x;
    g_s[i] = 0.0f; g_ps[i] = 0.0f; g_pc[i] = 0.0f;
    if (i == 0) { g_sum = 0.0f; g_cnt = 0.0f; }
}

__global__ void supcon_reduce() {
    int r = blockIdx.x * blockDim.x + threadIdx.x;
    float pcv = g_pc[r];
    float ls = 0.0f, lc = 0.0f;
    if (pcv > 0.0f) {
        float mlp = g_ps[r] / pcv - 10.0f - logf(g_s[r] + 1e-12f);
        ls = -mlp; lc = 1.0f;
    }
    #pragma unroll
    for (int o = 16; o >= 1; o >>= 1) {
        ls += __shfl_xor_sync(0xffffffffu, ls, o);
        lc += __shfl_xor_sync(0xffffffffu, lc, o);
    }
    if ((threadIdx.x & 31) == 0) {
        atomicAdd(&g_sum, ls);
        atomicAdd(&g_cnt, lc);
    }
}

__global__ void supcon_write(float* __restrict__ out) {
    float c = g_cnt;
    out[0] = (c > 0.0f) ? (g_sum / c) : 0.0f;
}

// ---- main kernel ------------------------------------------------------------
extern __shared__ float smem[];

__global__ __launch_bounds__(NTHR)
void supcon_main_kernel(const float* __restrict__ F,
                        const long long* __restrict__ L) {
    float* As = smem;                          // [DD][PADA] k-major, full K
    float* Bs = smem + SM_A_FLOATS;            // [64][PADB] k-major, half K
    float* colbuf = Bs;                        // [3][16][BN] = 24KB, aliases Bs
    int*   labA = (int*)(smem + SM_A_FLOATS + SM_B_FLOATS);   // [BM]
    int*   labB = labA + BM;                                  // [BN]

    const int tid = threadIdx.x;
    const int tx  = tid & 15;
    const int ty  = tid >> 4;
    const int myrow = ty * 8;

    // triangle schedule: pair (m, 63-m) = 65 tiles over 4 CTAs (17/16/16/16)
    const int p = blockIdx.x >> 2, q = blockIdx.x & 3;
    const int m = p, bb = 63 - p;
    const int Ta = 64 - m;                     // tiles in row-block m
    const int tstart = (q == 0) ? 0 : 17 + 16 * (q - 1);
    const int tend   = tstart + ((q == 0) ? 17 : 16);

    float s[8], ps[8], pc[8];
    #pragma unroll
    for (int r = 0; r < 8; r++) { s[r] = 0.f; ps[r] = 0.f; pc[r] = 0.f; }
    int la[8];
    int cur_i = -1;

    const int sc0 = bswz(2 * tx) * 4;
    const int sc1 = bswz(2 * tx + 1) * 4;

    for (int t = tstart; t < tend; t++) {
        int i, j;
        if (t < Ta) { i = m;  j = m + t; }
        else        { i = bb; j = bb + (t - Ta); }
        const int row0 = i * BM;
        const int col0 = j * BN;
        const bool diag = (i == j);
        const bool newA = (i != cur_i);

        // ---- row-block switch: flush row state, restage full-K A ----
        if (newA) {
            if (cur_i >= 0) {
                #pragma unroll
                for (int r = 0; r < 8; r++) {
                    float v = s[r], vp = ps[r], vc = pc[r];
                    #pragma unroll
                    for (int off = 8; off >= 1; off >>= 1) {
                        v  += __shfl_xor_sync(0xffffffffu, v,  off);
                        vp += __shfl_xor_sync(0xffffffffu, vp, off);
                        vc += __shfl_xor_sync(0xffffffffu, vc, off);
                    }
                    if (tx == 0) {
                        int gr = cur_i * BM + myrow + r;
                        atomicAdd(&g_s[gr],  v);
                        atomicAdd(&g_ps[gr], vp);
                        atomicAdd(&g_pc[gr], vc);
                    }
                    s[r] = 0.f; ps[r] = 0.f; pc[r] = 0.f;
                }
            }
            __syncthreads();                   // prior As readers done
            {
                const int c = tid >> 1, qq = tid & 1;
                const float4* src = (const float4*)(F + (size_t)(row0 + c) * DD);
                #pragma unroll
                for (int i2 = 0; i2 < 16; i2++) {
                    float4 v = src[qq + 2 * i2];
                    int k = (qq + 2 * i2) * 4;
                    As[(k + 0) * PADA + c] = v.x;
                    As[(k + 1) * PADA + c] = v.y;
                    As[(k + 2) * PADA + c] = v.z;
                    As[(k + 3) * PADA + c] = v.w;
                }
                if (tid < BM) labA[tid] = (int)L[row0 + tid];
            }
            cur_i = i;
        }

        // ---- accumulate over K in two halves (B restaged per half) ----
        unsigned long long acc[4][8];
        #pragma unroll
        for (int rp = 0; rp < 4; rp++)
            #pragma unroll
            for (int jj = 0; jj < 8; jj++) acc[rp][jj] = 0ull;

        #pragma unroll 1
        for (int h = 0; h < 2; h++) {
            const int kbase = h * 64;
            __syncthreads();                   // As ready / Bs free
            {
                const int cb = tid >> 1, qq = tid & 1;
                const float4* src =
                    (const float4*)(F + (size_t)(col0 + cb) * DD) + (kbase >> 2);
                const int ppos = bswz(cb >> 2) * 4 + (cb & 3);
                #pragma unroll
                for (int i2 = 0; i2 < 8; i2++) {
                    float4 v = src[qq + 2 * i2];
                    int k = (qq + 2 * i2) * 4;
                    Bs[(k + 0) * PADB + ppos] = v.x;
                    Bs[(k + 1) * PADB + ppos] = v.y;
                    Bs[(k + 2) * PADB + ppos] = v.z;
                    Bs[(k + 3) * PADB + ppos] = v.w;
                }
                if (h == 0 && tid < BN) labB[tid] = (int)L[col0 + tid];
            }
            __syncthreads();

            #pragma unroll 2
            for (int k = 0; k < 64; k++) {
                const float* arow = &As[(k + kbase) * PADA + myrow];
                ulonglong2 Ap0 = *(const ulonglong2*)(arow);
                ulonglong2 Ap1 = *(const ulonglong2*)(arow + 4);
                float4 b03 = *(const float4*)&Bs[k * PADB + sc0];
                float4 b47 = *(const float4*)&Bs[k * PADB + sc1];
                unsigned long long bd[8];
                bd[0] = dup2(b03.x); bd[1] = dup2(b03.y);
                bd[2] = dup2(b03.z); bd[3] = dup2(b03.w);
                bd[4] = dup2(b47.x); bd[5] = dup2(b47.y);
                bd[6] = dup2(b47.z); bd[7] = dup2(b47.w);
                #pragma unroll
                for (int jj = 0; jj < 8; jj++) {
                    FMA2(acc[0][jj], Ap0.x, bd[jj]);
                    FMA2(acc[1][jj], Ap0.y, bd[jj]);
                    FMA2(acc[2][jj], Ap1.x, bd[jj]);
                    FMA2(acc[3][jj], Ap1.y, bd[jj]);
                }
            }
        }

        if (newA) {
            #pragma unroll
            for (int r = 0; r < 8; r++) la[r] = labA[myrow + r];
        }

        // ---- epilogue: row credit always; column credit if off-diagonal ----
        float cs[8], cps[8], cpc[8];
        #pragma unroll
        for (int jj = 0; jj < 8; jj++) { cs[jj] = 0.f; cps[jj] = 0.f; cpc[jj] = 0.f; }

        #pragma unroll
        for (int jj = 0; jj < 8; jj++) {
            const int gj  = col0 + tx * 8 + jj;
            const int lbj = labB[tx * 8 + jj];
            #pragma unroll
            for (int rp = 0; rp < 4; rp++) {
                float v0, v1;
                unpack2(acc[rp][jj], v0, v1);
                #pragma unroll
                for (int e2 = 0; e2 < 2; e2++) {
                    const float v = e2 ? v1 : v0;
                    const int ii = 2 * rp + e2;
                    const int gi = row0 + myrow + ii;
                    if (!diag || gj != gi) {
                        float e = ex2f(fmaf(v, C_EXP, -C_EXP));
                        s[ii] += e; cs[jj] += e;
                        if (lbj == la[ii]) {
                            float sv = v * 10.0f;
                            ps[ii] += sv; pc[ii] += 1.0f;
                            cps[jj] += sv; cpc[jj] += 1.0f;
                        }
                    }
                }
            }
        }

        if (!diag) {
            __syncthreads();                   // Bs reads done by everyone
            #pragma unroll
            for (int jj = 0; jj < 8; jj++) {
                int cix = ty * BN + tx * 8 + jj;
                colbuf[cix]        = cs[jj];
                colbuf[2048 + cix] = cps[jj];
                colbuf[4096 + cix] = cpc[jj];
            }
            __syncthreads();
            if (tid < BN) {
                float a = 0.f, b = 0.f, c = 0.f;
                #pragma unroll
                for (int g2 = 0; g2 < 16; g2++) {
                    a += colbuf[g2 * BN + tid];
                    b += colbuf[2048 + g2 * BN + tid];
                    c += colbuf[4096 + g2 * BN + tid];
                }
                atomicAdd(&g_s[col0 + tid],  a);
                atomicAdd(&g_ps[col0 + tid], b);
                atomicAdd(&g_pc[col0 + tid], c);
            }
        }
    }

    // final flush of the last row-block's state
    #pragma unroll
    for (int r = 0; r < 8; r++) {
        float v = s[r], vp = ps[r], vc = pc[r];
        #pragma unroll
        for (int off = 8; off >= 1; off >>= 1) {
            v  += __shfl_xor_sync(0xffffffffu, v,  off);
            vp += __shfl_xor_sync(0xffffffffu, vp, off);
            vc += __shfl_xor_sync(0xffffffffu, vc, off);
        }
        if (tx == 0) {
            int gr = cur_i * BM + myrow + r;
            atomicAdd(&g_s[gr],  v);
            atomicAdd(&g_ps[gr], vp);
            atomicAdd(&g_pc[gr], vc);
        }
    }
}

// ---- launch ----------------------------------------------------------------
extern "C" void kernel_launch(void* const* d_in, const int* in_sizes, int n_in,
                              void* d_out, int out_size) {
    const float*     F = (const float*)d_in[0];
    const long long* L = (const long long*)d_in[1];
    float*           out = (float*)d_out;

    cudaFuncSetAttribute(supcon_main_kernel,
                         cudaFuncAttributeMaxDynamicSharedMemorySize, SMEM_TOTAL);

    supcon_zero<<<BSZ / 256, 256>>>();
    supcon_main_kernel<<<128, NTHR, SMEM_TOTAL>>>(F, L);
    supcon_reduce<<<BSZ / 256, 256>>>();
    supcon_write<<<1, 1>>>(out);
}

// round 15
// speedup vs baseline: 3.7165x; 1.3409x over previous
#include <cuda_runtime.h>
#include <math.h>
#include <cstdint>

// ============================================================================
// SupConLoss, B=8192, D=128, T=0.1. Round 15 (= R14 minus the compile bug):
// 148-CTA balanced triangle + register-prefetched B-half staging. Hot loop
// verbatim from R13 (FMA2-pipe bound at 128 cyc/k per SM).
//
// Schedule: 2080 upper-tri 128x128 tiles in pair-major order (pair p = rows
// {p, 63-p}, 65 contiguous tiles); CTA c owns [c*2080/148,(c+1)*2080/148)
// (14-15 tiles, <=3 A-restages). Diag tiles: row credit only, elem diag
// masked. Off-diag: row + column (transpose) credit.
//
// TOOLCHAIN RULES (R3-R13): no cp.async/ldmatrix/mma.sync/tcgen05; __device__
// arrays scalar-access only, no align attrs (vector access to device symbols
// => CUDA 717); fma.rn.f32x2 is real FFMA2 and safe; smem <= ~103KB proven.
//
// Math: constant shift 10 (log-softmax shift-invariance; diag sim == 1
// dominates). loss = mean_{pc>0} -(ps/pc - 10 - log(s+1e-12)), ps pre-scaled.
// ============================================================================

#define BSZ   8192
#define DD    128
#define BM    128
#define BN    128
#define NTHR  256
#define NCTA  148
#define NTT   2080                       // 64*65/2 upper-tri tiles
#define PADA  132
#define PADB  132
#define C_EXP 14.4269504088896341f

#define SM_A_FLOATS (DD * PADA)          // 16896
#define SM_B_FLOATS (64 * PADB)          // 8448 (half-k B)
#define SMEM_TOTAL  ((SM_A_FLOATS + SM_B_FLOATS) * 4 + (BM + BN) * 4)  // 102400

// ---- device scratch: plain arrays, scalar access only ----------------------
__device__ float g_s[BSZ];
__device__ float g_ps[BSZ];
__device__ float g_pc[BSZ];
__device__ float g_sum;
__device__ float g_cnt;

// ---- helpers ---------------------------------------------------------------
__device__ __forceinline__ float ex2f(float x) {
    float y;
    asm("ex2.approx.ftz.f32 %0, %1;" : "=f"(y) : "f"(x));
    return y;
}
__device__ __forceinline__ void unpack2(unsigned long long v, float& x, float& y) {
    asm("mov.b64 {%0, %1}, %2;" : "=f"(x), "=f"(y) : "l"(v));
}
__device__ __forceinline__ unsigned long long dup2(float x) {
    unsigned long long r;
    asm("mov.b64 %0, {%1, %1};" : "=l"(r) : "f"(x));
    return r;
}
#define FMA2(acc, a, b) \
    asm("fma.rn.f32x2 %0, %1, %2, %0;" : "+l"(acc) : "l"(a), "l"(b))
__device__ __forceinline__ int bswz(int cc) { return cc ^ (cc >> 3); }

// ---- aux kernels (verbatim from passing R12/R13) ----------------------------
__global__ void supcon_zero() {
    int i = blockIdx.x * blockDim.x + threadIdx.x;
    g_s[i] = 0.0f; g_ps[i] = 0.0f; g_pc[i] = 0.0f;
    if (i == 0) { g_sum = 0.0f; g_cnt = 0.0f; }
}

__global__ void supcon_reduce() {
    int r = blockIdx.x * blockDim.x + threadIdx.x;
    float pcv = g_pc[r];
    float ls = 0.0f, lc = 0.0f;
    if (pcv > 0.0f) {
        float mlp = g_ps[r] / pcv - 10.0f - logf(g_s[r] + 1e-12f);
        ls = -mlp; lc = 1.0f;
    }
    #pragma unroll
    for (int o = 16; o >= 1; o >>= 1) {
        ls += __shfl_xor_sync(0xffffffffu, ls, o);
        lc += __shfl_xor_sync(0xffffffffu, lc, o);
    }
    if ((threadIdx.x & 31) == 0) {
        atomicAdd(&g_sum, ls);
        atomicAdd(&g_cnt, lc);
    }
}

__global__ void supcon_write(float* __restrict__ out) {
    float c = g_cnt;
    out[0] = (c > 0.0f) ? (g_sum / c) : 0.0f;
}

// ---- main kernel ------------------------------------------------------------
extern __shared__ float smem[];

__global__ __launch_bounds__(NTHR, 1)
void supcon_main_kernel(const float* __restrict__ F,
                        const long long* __restrict__ L) {
    float* As = smem;                          // [DD][PADA] k-major, full K
    float* Bs = smem + SM_A_FLOATS;            // [64][PADB] k-major, half K
    float* colbuf = Bs;                        // [3][16][BN] = 24KB, aliases Bs
    int*   labA = (int*)(smem + SM_A_FLOATS + SM_B_FLOATS);   // [BM]
    int*   labB = labA + BM;                                  // [BN]

    const int tid = threadIdx.x;
    const int tx  = tid & 15;
    const int ty  = tid >> 4;
    const int myrow = ty * 8;

    // flat balanced schedule over NCTA CTAs
    const int g0 = (int)(((long long)blockIdx.x * NTT) / NCTA);
    const int g1 = (int)(((long long)(blockIdx.x + 1) * NTT) / NCTA);

    float s[8], ps[8], pc[8];
    #pragma unroll
    for (int r = 0; r < 8; r++) { s[r] = 0.f; ps[r] = 0.f; pc[r] = 0.f; }
    int la[8];
    int cur_i = -1;

    const int sc0 = bswz(2 * tx) * 4;
    const int sc1 = bswz(2 * tx + 1) * 4;
    const int cb = tid >> 1, qq = tid & 1;     // staging geometry
    const int ppos = bswz(cb >> 2) * 4 + (cb & 3);

    for (int gg = g0; gg < g1; gg++) {
        const int p = gg / 65, o = gg % 65;
        const int ra = 64 - p;                 // tiles in row p
        int i, j;
        if (o < ra) { i = p;      j = p + o; }
        else        { i = 63 - p; j = (63 - p) + (o - ra); }
        const int row0 = i * BM;
        const int col0 = j * BN;
        const bool diag = (i == j);
        const bool newA = (i != cur_i);

        // ---- row-block switch: flush row state, restage full-K A ----
        if (newA) {
            if (cur_i >= 0) {
                #pragma unroll
                for (int r = 0; r < 8; r++) {
                    float v = s[r], vp = ps[r], vc = pc[r];
                    #pragma unroll
                    for (int off = 8; off >= 1; off >>= 1) {
                        v  += __shfl_xor_sync(0xffffffffu, v,  off);
                        vp += __shfl_xor_sync(0xffffffffu, vp, off);
                        vc += __shfl_xor_sync(0xffffffffu, vc, off);
                    }
                    if (tx == 0) {
                        int gr = cur_i * BM + myrow + r;
                        atomicAdd(&g_s[gr],  v);
                        atomicAdd(&g_ps[gr], vp);
                        atomicAdd(&g_pc[gr], vc);
                    }
                    s[r] = 0.f; ps[r] = 0.f; pc[r] = 0.f;
                }
            }
            __syncthreads();                   // prior As readers done
            {
                const float4* src = (const float4*)(F + (size_t)(row0 + cb) * DD);
                #pragma unroll
                for (int i2 = 0; i2 < 16; i2++) {
                    float4 v = src[qq + 2 * i2];
                    int k = (qq + 2 * i2) * 4;
                    As[(k + 0) * PADA + cb] = v.x;
                    As[(k + 1) * PADA + cb] = v.y;
                    As[(k + 2) * PADA + cb] = v.z;
                    As[(k + 3) * PADA + cb] = v.w;
                }
                if (tid < BM) labA[tid] = (int)L[row0 + tid];
            }
            cur_i = i;
        }

        unsigned long long acc[4][8];
        #pragma unroll
        for (int rp = 0; rp < 4; rp++)
            #pragma unroll
            for (int jj = 0; jj < 8; jj++) acc[rp][jj] = 0ull;

        const float4* bsrc = (const float4*)(F + (size_t)(col0 + cb) * DD);

        // ---- half 0: stage + prefetch half1 to regs ----
        __syncthreads();                       // As ready / Bs free
        {
            #pragma unroll
            for (int i2 = 0; i2 < 8; i2++) {
                float4 v = bsrc[qq + 2 * i2];
                int k = (qq + 2 * i2) * 4;
                Bs[(k + 0) * PADB + ppos] = v.x;
                Bs[(k + 1) * PADB + ppos] = v.y;
                Bs[(k + 2) * PADB + ppos] = v.z;
                Bs[(k + 3) * PADB + ppos] = v.w;
            }
            if (tid < BN) labB[tid] = (int)L[col0 + tid];
        }
        float4 Rv1[8];
        #pragma unroll
        for (int i2 = 0; i2 < 8; i2++) Rv1[i2] = bsrc[16 + qq + 2 * i2];
        __syncthreads();

        #pragma unroll 2
        for (int k = 0; k < 64; k++) {
            const float* arow = &As[k * PADA + myrow];
            ulonglong2 Ap0 = *(const ulonglong2*)(arow);
            ulonglong2 Ap1 = *(const ulonglong2*)(arow + 4);
            float4 b03 = *(const float4*)&Bs[k * PADB + sc0];
            float4 b47 = *(const float4*)&Bs[k * PADB + sc1];
            unsigned long long bd[8];
            bd[0] = dup2(b03.x); bd[1] = dup2(b03.y);
            bd[2] = dup2(b03.z); bd[3] = dup2(b03.w);
            bd[4] = dup2(b47.x); bd[5] = dup2(b47.y);
            bd[6] = dup2(b47.z); bd[7] = dup2(b47.w);
            #pragma unroll
            for (int jj = 0; jj < 8; jj++) {
                FMA2(acc[0][jj], Ap0.x, bd[jj]);
                FMA2(acc[1][jj], Ap0.y, bd[jj]);
                FMA2(acc[2][jj], Ap1.x, bd[jj]);
                FMA2(acc[3][jj], Ap1.y, bd[jj]);
            }
        }

        // ---- half 1: STS from prefetched regs ----
        __syncthreads();                       // half0 reads done
        #pragma unroll
        for (int i2 = 0; i2 < 8; i2++) {
            int k = (qq + 2 * i2) * 4;
            Bs[(k + 0) * PADB + ppos] = Rv1[i2].x;
            Bs[(k + 1) * PADB + ppos] = Rv1[i2].y;
            Bs[(k + 2) * PADB + ppos] = Rv1[i2].z;
            Bs[(k + 3) * PADB + ppos] = Rv1[i2].w;
        }
        __syncthreads();

        #pragma unroll 2
        for (int k = 0; k < 64; k++) {
            const float* arow = &As[(k + 64) * PADA + myrow];
            ulonglong2 Ap0 = *(const ulonglong2*)(arow);
            ulonglong2 Ap1 = *(const ulonglong2*)(arow + 4);
            float4 b03 = *(const float4*)&Bs[k * PADB + sc0];
            float4 b47 = *(const float4*)&Bs[k * PADB + sc1];
            unsigned long long bd[8];
            bd[0] = dup2(b03.x); bd[1] = dup2(b03.y);
            bd[2] = dup2(b03.z); bd[3] = dup2(b03.w);
            bd[4] = dup2(b47.x); bd[5] = dup2(b47.y);
            bd[6] = dup2(b47.z); bd[7] = dup2(b47.w);
            #pragma unroll
            for (int jj = 0; jj < 8; jj++) {
                FMA2(acc[0][jj], Ap0.x, bd[jj]);
                FMA2(acc[1][jj], Ap0.y, bd[jj]);
                FMA2(acc[2][jj], Ap1.x, bd[jj]);
                FMA2(acc[3][jj], Ap1.y, bd[jj]);
            }
        }

        if (newA) {
            #pragma unroll
            for (int r = 0; r < 8; r++) la[r] = labA[myrow + r];
        }

        // ---- epilogue: row credit always; column credit if off-diagonal ----
        float cs[8], cps[8], cpc[8];
        #pragma unroll
        for (int jj = 0; jj < 8; jj++) { cs[jj] = 0.f; cps[jj] = 0.f; cpc[jj] = 0.f; }

        #pragma unroll
        for (int jj = 0; jj < 8; jj++) {
            const int gj  = col0 + tx * 8 + jj;
            const int lbj = labB[tx * 8 + jj];
            #pragma unroll
            for (int rp = 0; rp < 4; rp++) {
                float v0, v1;
                unpack2(acc[rp][jj], v0, v1);
                #pragma unroll
                for (int e2 = 0; e2 < 2; e2++) {
                    const float v = e2 ? v1 : v0;
                    const int ii = 2 * rp + e2;
                    const int gi = row0 + myrow + ii;
                    if (!diag || gj != gi) {
                        float e = ex2f(fmaf(v, C_EXP, -C_EXP));
                        s[ii] += e; cs[jj] += e;
                        if (lbj == la[ii]) {
                            float sv = v * 10.0f;
                            ps[ii] += sv; pc[ii] += 1.0f;
                            cps[jj] += sv; cpc[jj] += 1.0f;
                        }
                    }
                }
            }
        }

        if (!diag) {
            __syncthreads();                   // Bs reads done by everyone
            #pragma unroll
            for (int jj = 0; jj < 8; jj++) {
                int cix = ty * BN + tx * 8 + jj;
                colbuf[cix]        = cs[jj];
                colbuf[2048 + cix] = cps[jj];
                colbuf[4096 + cix] = cpc[jj];
            }
            __syncthreads();
            if (tid < BN) {
                float a = 0.f, b = 0.f, c = 0.f;
                #pragma unroll
                for (int g2 = 0; g2 < 16; g2++) {
                    a += colbuf[g2 * BN + tid];
                    b += colbuf[2048 + g2 * BN + tid];
                    c += colbuf[4096 + g2 * BN + tid];
                }
                atomicAdd(&g_s[col0 + tid],  a);
                atomicAdd(&g_ps[col0 + tid], b);
                atomicAdd(&g_pc[col0 + tid], c);
            }
        }
    }

    // final flush of the last row-block's state
    if (cur_i >= 0) {
        #pragma unroll
        for (int r = 0; r < 8; r++) {
            float v = s[r], vp = ps[r], vc = pc[r];
            #pragma unroll
            for (int off = 8; off >= 1; off >>= 1) {
                v  += __shfl_xor_sync(0xffffffffu, v,  off);
                vp += __shfl_xor_sync(0xffffffffu, vp, off);
                vc += __shfl_xor_sync(0xffffffffu, vc, off);
            }
            if (tx == 0) {
                int gr = cur_i * BM + myrow + r;
                atomicAdd(&g_s[gr],  v);
                atomicAdd(&g_ps[gr], vp);
                atomicAdd(&g_pc[gr], vc);
            }
        }
    }
}

// ---- launch ----------------------------------------------------------------
extern "C" void kernel_launch(void* const* d_in, const int* in_sizes, int n_in,
                              void* d_out, int out_size) {
    const float*     F = (const float*)d_in[0];
    const long long* L = (const long long*)d_in[1];
    float*           out = (float*)d_out;

    cudaFuncSetAttribute(supcon_main_kernel,
                         cudaFuncAttributeMaxDynamicSharedMemorySize, SMEM_TOTAL);

    supcon_zero<<<BSZ / 256, 256>>>();
    supcon_main_kernel<<<NCTA, NTHR, SMEM_TOTAL>>>(F, L);
    supcon_reduce<<<BSZ / 256, 256>>>();
    supcon_write<<<1, 1>>>(out);
}

// round 16
// speedup vs baseline: 3.7267x; 1.0028x over previous
#include <cuda_runtime.h>
#include <math.h>
#include <cstdint>

// ============================================================================
// SupConLoss, B=8192, D=128, T=0.1. Round 15 (= R14 minus the compile bug):
// 148-CTA balanced triangle + register-prefetched B-half staging. Hot loop
// verbatim from R13 (FMA2-pipe bound at 128 cyc/k per SM).
//
// Schedule: 2080 upper-tri 128x128 tiles in pair-major order (pair p = rows
// {p, 63-p}, 65 contiguous tiles); CTA c owns [c*2080/148,(c+1)*2080/148)
// (14-15 tiles, <=3 A-restages). Diag tiles: row credit only, elem diag
// masked. Off-diag: row + column (transpose) credit.
//
// TOOLCHAIN RULES (R3-R13): no cp.async/ldmatrix/mma.sync/tcgen05; __device__
// arrays scalar-access only, no align attrs (vector access to device symbols
// => CUDA 717); fma.rn.f32x2 is real FFMA2 and safe; smem <= ~103KB proven.
//
// Math: constant shift 10 (log-softmax shift-invariance; diag sim == 1
// dominates). loss = mean_{pc>0} -(ps/pc - 10 - log(s+1e-12)), ps pre-scaled.
// ============================================================================

#define BSZ   8192
#define DD    128
#define BM    128
#define BN    128
#define NTHR  256
#define NCTA  148
#define NTT   2080                       // 64*65/2 upper-tri tiles
#define PADA  132
#define PADB  132
#define C_EXP 14.4269504088896341f

#define SM_A_FLOATS (DD * PADA)          // 16896
#define SM_B_FLOATS (64 * PADB)          // 8448 (half-k B)
#define SMEM_TOTAL  ((SM_A_FLOATS + SM_B_FLOATS) * 4 + (BM + BN) * 4)  // 102400

// ---- device scratch: plain arrays, scalar access only ----------------------
__device__ float g_s[BSZ];
__device__ float g_ps[BSZ];
__device__ float g_pc[BSZ];
__device__ float g_sum;
__device__ float g_cnt;

// ---- helpers ---------------------------------------------------------------
__device__ __forceinline__ float ex2f(float x) {
    float y;
    asm("ex2.approx.ftz.f32 %0, %1;" : "=f"(y) : "f"(x));
    return y;
}
__device__ __forceinline__ void unpack2(unsigned long long v, float& x, float& y) {
    asm("mov.b64 {%0, %1}, %2;" : "=f"(x), "=f"(y) : "l"(v));
}
__device__ __forceinline__ unsigned long long dup2(float x) {
    unsigned long long r;
    asm("mov.b64 %0, {%1, %1};" : "=l"(r) : "f"(x));
    return r;
}
#define FMA2(acc, a, b) \
    asm("fma.rn.f32x2 %0, %1, %2, %0;" : "+l"(acc) : "l"(a), "l"(b))
__device__ __forceinline__ int bswz(int cc) { return cc ^ (cc >> 3); }

// ---- aux kernels (verbatim from passing R12/R13) ----------------------------
__global__ void supcon_zero() {
    int i = blockIdx.x * blockDim.x + threadIdx.x;
    g_s[i] = 0.0f; g_ps[i] = 0.0f; g_pc[i] = 0.0f;
    if (i == 0) { g_sum = 0.0f; g_cnt = 0.0f; }
}

__global__ void supcon_reduce() {
    int r = blockIdx.x * blockDim.x + threadIdx.x;
    float pcv = g_pc[r];
    float ls = 0.0f, lc = 0.0f;
    if (pcv > 0.0f) {
        float mlp = g_ps[r] / pcv - 10.0f - logf(g_s[r] + 1e-12f);
        ls = -mlp; lc = 1.0f;
    }
    #pragma unroll
    for (int o = 16; o >= 1; o >>= 1) {
        ls += __shfl_xor_sync(0xffffffffu, ls, o);
        lc += __shfl_xor_sync(0xffffffffu, lc, o);
    }
    if ((threadIdx.x & 31) == 0) {
        atomicAdd(&g_sum, ls);
        atomicAdd(&g_cnt, lc);
    }
}

__global__ void supcon_write(float* __restrict__ out) {
    float c = g_cnt;
    out[0] = (c > 0.0f) ? (g_sum / c) : 0.0f;
}

// ---- main kernel ------------------------------------------------------------
extern __shared__ float smem[];

__global__ __launch_bounds__(NTHR, 1)
void supcon_main_kernel(const float* __restrict__ F,
                        const long long* __restrict__ L) {
    float* As = smem;                          // [DD][PADA] k-major, full K
    float* Bs = smem + SM_A_FLOATS;            // [64][PADB] k-major, half K
    float* colbuf = Bs;                        // [3][16][BN] = 24KB, aliases Bs
    int*   labA = (int*)(smem + SM_A_FLOATS + SM_B_FLOATS);   // [BM]
    int*   labB = labA + BM;                                  // [BN]

    const int tid = threadIdx.x;
    const int tx  = tid & 15;
    const int ty  = tid >> 4;
    const int myrow = ty * 8;

    // flat balanced schedule over NCTA CTAs
    const int g0 = (int)(((long long)blockIdx.x * NTT) / NCTA);
    const int g1 = (int)(((long long)(blockIdx.x + 1) * NTT) / NCTA);

    float s[8], ps[8], pc[8];
    #pragma unroll
    for (int r = 0; r < 8; r++) { s[r] = 0.f; ps[r] = 0.f; pc[r] = 0.f; }
    int la[8];
    int cur_i = -1;

    const int sc0 = bswz(2 * tx) * 4;
    const int sc1 = bswz(2 * tx + 1) * 4;
    const int cb = tid >> 1, qq = tid & 1;     // staging geometry
    const int ppos = bswz(cb >> 2) * 4 + (cb & 3);

    for (int gg = g0; gg < g1; gg++) {
        const int p = gg / 65, o = gg % 65;
        const int ra = 64 - p;                 // tiles in row p
        int i, j;
        if (o < ra) { i = p;      j = p + o; }
        else        { i = 63 - p; j = (63 - p) + (o - ra); }
        const int row0 = i * BM;
        const int col0 = j * BN;
        const bool diag = (i == j);
        const bool newA = (i != cur_i);

        // ---- row-block switch: flush row state, restage full-K A ----
        if (newA) {
            if (cur_i >= 0) {
                #pragma unroll
                for (int r = 0; r < 8; r++) {
                    float v = s[r], vp = ps[r], vc = pc[r];
                    #pragma unroll
                    for (int off = 8; off >= 1; off >>= 1) {
                        v  += __shfl_xor_sync(0xffffffffu, v,  off);
                        vp += __shfl_xor_sync(0xffffffffu, vp, off);
                        vc += __shfl_xor_sync(0xffffffffu, vc, off);
                    }
                    if (tx == 0) {
                        int gr = cur_i * BM + myrow + r;
                        atomicAdd(&g_s[gr],  v);
                        atomicAdd(&g_ps[gr], vp);
                        atomicAdd(&g_pc[gr], vc);
                    }
                    s[r] = 0.f; ps[r] = 0.f; pc[r] = 0.f;
                }
            }
            __syncthreads();                   // prior As readers done
            {
                const float4* src = (const float4*)(F + (size_t)(row0 + cb) * DD);
                #pragma unroll
                for (int i2 = 0; i2 < 16; i2++) {
                    float4 v = src[qq + 2 * i2];
                    int k = (qq + 2 * i2) * 4;
                    As[(k + 0) * PADA + cb] = v.x;
                    As[(k + 1) * PADA + cb] = v.y;
                    As[(k + 2) * PADA + cb] = v.z;
                    As[(k + 3) * PADA + cb] = v.w;
                }
                if (tid < BM) labA[tid] = (int)L[row0 + tid];
            }
            cur_i = i;
        }

        unsigned long long acc[4][8];
        #pragma unroll
        for (int rp = 0; rp < 4; rp++)
            #pragma unroll
            for (int jj = 0; jj < 8; jj++) acc[rp][jj] = 0ull;

        const float4* bsrc = (const float4*)(F + (size_t)(col0 + cb) * DD);

        // ---- half 0: stage + prefetch half1 to regs ----
        __syncthreads();                       // As ready / Bs free
        {
            #pragma unroll
            for (int i2 = 0; i2 < 8; i2++) {
                float4 v = bsrc[qq + 2 * i2];
                int k = (qq + 2 * i2) * 4;
                Bs[(k + 0) * PADB + ppos] = v.x;
                Bs[(k + 1) * PADB + ppos] = v.y;
                Bs[(k + 2) * PADB + ppos] = v.z;
                Bs[(k + 3) * PADB + ppos] = v.w;
            }
            if (tid < BN) labB[tid] = (int)L[col0 + tid];
        }
        float4 Rv1[8];
        #pragma unroll
        for (int i2 = 0; i2 < 8; i2++) Rv1[i2] = bsrc[16 + qq + 2 * i2];
        __syncthreads();

        #pragma unroll 2
        for (int k = 0; k < 64; k++) {
            const float* arow = &As[k * PADA + myrow];
            ulonglong2 Ap0 = *(const ulonglong2*)(arow);
            ulonglong2 Ap1 = *(const ulonglong2*)(arow + 4);
            float4 b03 = *(const float4*)&Bs[k * PADB + sc0];
            float4 b47 = *(const float4*)&Bs[k * PADB + sc1];
            unsigned long long bd[8];
            bd[0] = dup2(b03.x); bd[1] = dup2(b03.y);
            bd[2] = dup2(b03.z); bd[3] = dup2(b03.w);
            bd[4] = dup2(b47.x); bd[5] = dup2(b47.y);
            bd[6] = dup2(b47.z); bd[7] = dup2(b47.w);
            #pragma unroll
            for (int jj = 0; jj < 8; jj++) {
                FMA2(acc[0][jj], Ap0.x, bd[jj]);
                FMA2(acc[1][jj], Ap0.y, bd[jj]);
                FMA2(acc[2][jj], Ap1.x, bd[jj]);
                FMA2(acc[3][jj], Ap1.y, bd[jj]);
            }
        }

        // ---- half 1: STS from prefetched regs ----
        __syncthreads();                       // half0 reads done
        #pragma unroll
        for (int i2 = 0; i2 < 8; i2++) {
            int k = (qq + 2 * i2) * 4;
            Bs[(k + 0) * PADB + ppos] = Rv1[i2].x;
            Bs[(k + 1) * PADB + ppos] = Rv1[i2].y;
            Bs[(k + 2) * PADB + ppos] = Rv1[i2].z;
            Bs[(k + 3) * PADB + ppos] = Rv1[i2].w;
        }
        __syncthreads();

        #pragma unroll 2
        for (int k = 0; k < 64; k++) {
            const float* arow = &As[(k + 64) * PADA + myrow];
            ulonglong2 Ap0 = *(const ulonglong2*)(arow);
            ulonglong2 Ap1 = *(const ulonglong2*)(arow + 4);
            float4 b03 = *(const float4*)&Bs[k * PADB + sc0];
            float4 b47 = *(const float4*)&Bs[k * PADB + sc1];
            unsigned long long bd[8];
            bd[0] = dup2(b03.x); bd[1] = dup2(b03.y);
            bd[2] = dup2(b03.z); bd[3] = dup2(b03.w);
            bd[4] = dup2(b47.x); bd[5] = dup2(b47.y);
            bd[6] = dup2(b47.z); bd[7] = dup2(b47.w);
            #pragma unroll
            for (int jj = 0; jj < 8; jj++) {
                FMA2(acc[0][jj], Ap0.x, bd[jj]);
                FMA2(acc[1][jj], Ap0.y, bd[jj]);
                FMA2(acc[2][jj], Ap1.x, bd[jj]);
                FMA2(acc[3][jj], Ap1.y, bd[jj]);
            }
        }

        if (newA) {
            #pragma unroll
            for (int r = 0; r < 8; r++) la[r] = labA[myrow + r];
        }

        // ---- epilogue: row credit always; column credit if off-diagonal ----
        float cs[8], cps[8], cpc[8];
        #pragma unroll
        for (int jj = 0; jj < 8; jj++) { cs[jj] = 0.f; cps[jj] = 0.f; cpc[jj] = 0.f; }

        #pragma unroll
        for (int jj = 0; jj < 8; jj++) {
            const int gj  = col0 + tx * 8 + jj;
            const int lbj = labB[tx * 8 + jj];
            #pragma unroll
            for (int rp = 0; rp < 4; rp++) {
                float v0, v1;
                unpack2(acc[rp][jj], v0, v1);
                #pragma unroll
                for (int e2 = 0; e2 < 2; e2++) {
                    const float v = e2 ? v1 : v0;
                    const int ii = 2 * rp + e2;
                    const int gi = row0 + myrow + ii;
                    if (!diag || gj != gi) {
                        float e = ex2f(fmaf(v, C_EXP, -C_EXP));
                        s[ii] += e; cs[jj] += e;
                        if (lbj == la[ii]) {
                            float sv = v * 10.0f;
                            ps[ii] += sv; pc[ii] += 1.0f;
                            cps[jj] += sv; cpc[jj] += 1.0f;
                        }
                    }
                }
            }
        }

        if (!diag) {
            __syncthreads();                   // Bs reads done by everyone
            #pragma unroll
            for (int jj = 0; jj < 8; jj++) {
                int cix = ty * BN + tx * 8 + jj;
                colbuf[cix]        = cs[jj];
                colbuf[2048 + cix] = cps[jj];
                colbuf[4096 + cix] = cpc[jj];
            }
            __syncthreads();
            if (tid < BN) {
                float a = 0.f, b = 0.f, c = 0.f;
                #pragma unroll
                for (int g2 = 0; g2 < 16; g2++) {
                    a += colbuf[g2 * BN + tid];
                    b += colbuf[2048 + g2 * BN + tid];
                    c += colbuf[4096 + g2 * BN + tid];
                }
                atomicAdd(&g_s[col0 + tid],  a);
                atomicAdd(&g_ps[col0 + tid], b);
                atomicAdd(&g_pc[col0 + tid], c);
            }
        }
    }

    // final flush of the last row-block's state
    if (cur_i >= 0) {
        #pragma unroll
        for (int r = 0; r < 8; r++) {
            float v = s[r], vp = ps[r], vc = pc[r];
            #pragma unroll
            for (int off = 8; off >= 1; off >>= 1) {
                v  += __shfl_xor_sync(0xffffffffu, v,  off);
                vp += __shfl_xor_sync(0xffffffffu, vp, off);
                vc += __shfl_xor_sync(0xffffffffu, vc, off);
            }
            if (tx == 0) {
                int gr = cur_i * BM + myrow + r;
                atomicAdd(&g_s[gr],  v);
                atomicAdd(&g_ps[gr], vp);
                atomicAdd(&g_pc[gr], vc);
            }
        }
    }
}

// ---- launch ----------------------------------------------------------------
extern "C" void kernel_launch(void* const* d_in, const int* in_sizes, int n_in,
                              void* d_out, int out_size) {
    const float*     F = (const float*)d_in[0];
    const long long* L = (const long long*)d_in[1];
    float*           out = (float*)d_out;

    cudaFuncSetAttribute(supcon_main_kernel,
                         cudaFuncAttributeMaxDynamicSharedMemorySize, SMEM_TOTAL);

    supcon_zero<<<BSZ / 256, 256>>>();
    supcon_main_kernel<<<NCTA, NTHR, SMEM_TOTAL>>>(F, L);
    supcon_reduce<<<BSZ / 256, 256>>>();
    supcon_write<<<1, 1>>>(out);
}